// round 3
// baseline (speedup 1.0000x reference)
#include <cuda_runtime.h>
#include <cuda_bf16.h>
#include <cuda_fp16.h>
#include <cstdint>

// ---------------------------------------------------------------------------
// DeformableAttention (B=8, N=4096, C=256, S=4, NH=8, NL=1, NP=4, HD=32)
//
// bf16x3 split-precision tensor-core pipeline, fp16 sampling map:
//   1. prep: vmean = mean_s v; transpose+split Wv,Wo -> bf16 hi/lo;
//            bfold = bq@[Woff|Wattn] + [boff|battn]
//   2. fold: WfT = (Wq @ [Woff|Wattn])^T split -> bf16 hi/lo
//   3. offattn = q @ Wfold + bfold              (mma, 32768 x 96, fp32 out)
//   4. vpm     = vmean @ Wv + bv                (mma, 4096 x 256, fp16 out)
//   5. sampling: softmax + bilinear gather (fp16 map) -> pre (fp32)
//   6. out     = pre @ Wo + bo                  (mma, 32768 x 256, fp32 out)
// ---------------------------------------------------------------------------

namespace {
constexpr int Bn   = 8;
constexpr int Nn   = 4096;
constexpr int Cc   = 256;   // K for all GEMMs
constexpr int NHh  = 8;
constexpr int NPp  = 4;
constexpr int HDd  = 32;
constexpr int ROWS = Bn * Nn;    // 32768
constexpr int GW   = 64;
}

// -------------------- scratch (static device globals) ----------------------
__device__ __align__(16) float g_vmean[Nn * Cc];
__device__ __align__(16) __half g_vpm_h[Nn * Cc];
__device__ __align__(16) float g_bfold[96];
__device__ __align__(16) __nv_bfloat16 g_WvT_hi[Cc * Cc];
__device__ __align__(16) __nv_bfloat16 g_WvT_lo[Cc * Cc];
__device__ __align__(16) __nv_bfloat16 g_WoT_hi[Cc * Cc];
__device__ __align__(16) __nv_bfloat16 g_WoT_lo[Cc * Cc];
__device__ __align__(16) __nv_bfloat16 g_WfT_hi[96 * Cc];
__device__ __align__(16) __nv_bfloat16 g_WfT_lo[96 * Cc];
__device__ __align__(16) float g_offattn[(size_t)ROWS * 96];
__device__ __align__(16) float g_pre[(size_t)ROWS * Cc];

// -------------------- helpers ----------------------------------------------
__device__ __forceinline__ void mma_bf16(float c[4], const uint32_t a[4],
                                         const uint32_t b[2]) {
    asm volatile(
        "mma.sync.aligned.m16n8k16.row.col.f32.bf16.bf16.f32 "
        "{%0,%1,%2,%3}, {%4,%5,%6,%7}, {%8,%9}, {%0,%1,%2,%3};\n"
        : "+f"(c[0]), "+f"(c[1]), "+f"(c[2]), "+f"(c[3])
        : "r"(a[0]), "r"(a[1]), "r"(a[2]), "r"(a[3]), "r"(b[0]), "r"(b[1]));
}

__device__ __forceinline__ void split_bf16(float x, __nv_bfloat16& h,
                                           __nv_bfloat16& l) {
    h = __float2bfloat16(x);
    l = __float2bfloat16(x - __bfloat162float(h));
}

// -------------------- split-bf16 GEMM: C = A(fp32) @ Bt^T + bias ----------
// A: M x K fp32 (K = 256). Bt: N x K bf16 (hi/lo). C: M x N (fp32 or fp16).
// Block tile 128 x BN, BK = 32. 8 warps (4 x 2), warp tile 32 x (BN/2).
template <int BN, bool HALF_OUT>
__global__ void __launch_bounds__(256)
gemm_bf16x3(const float* __restrict__ A,
            const __nv_bfloat16* __restrict__ BtHi,
            const __nv_bfloat16* __restrict__ BtLo,
            const float* __restrict__ bias, void* __restrict__ Cout,
            int M, int N) {
    constexpr int BM = 128, BK = 32, K = Cc;
    constexpr int LDS_ = BK + 8;
    constexpr int WN = BN / 2;
    constexpr int NT = WN / 8;
    constexpr int BCH = BN * 4;

    __shared__ __nv_bfloat16 AsH[BM * LDS_];
    __shared__ __nv_bfloat16 AsL[BM * LDS_];
    __shared__ __nv_bfloat16 BsH[BN * LDS_];
    __shared__ __nv_bfloat16 BsL[BN * LDS_];

    const int t = threadIdx.x;
    const int w = t >> 5, l = t & 31;
    const int wm = w & 3, wn = w >> 2;
    const int g = l >> 2, q = l & 3;
    const int blockRow = blockIdx.y * BM;
    const int blockCol = blockIdx.x * BN;

    const int arow = t >> 1, aseg = (t & 1) * 16;
    constexpr int NCH = (BCH + 255) / 256;

    float acc[2][NT][4];
#pragma unroll
    for (int i = 0; i < 2; i++)
#pragma unroll
        for (int j = 0; j < NT; j++)
#pragma unroll
            for (int x = 0; x < 4; x++) acc[i][j][x] = 0.f;

    float4 af[4];
    uint4 bhv[NCH], blv[NCH];

    {
        const float* src = A + (size_t)(blockRow + arow) * K + aseg;
#pragma unroll
        for (int i = 0; i < 4; i++) af[i] = *(const float4*)(src + i * 4);
#pragma unroll
        for (int c = 0; c < NCH; c++) {
            int ch = t + c * 256;
            if (ch < BCH) {
                int brow = ch >> 2, bseg = (ch & 3) * 8;
                bhv[c] = *(const uint4*)(BtHi + (size_t)(blockCol + brow) * K + bseg);
                blv[c] = *(const uint4*)(BtLo + (size_t)(blockCol + brow) * K + bseg);
            }
        }
    }

    for (int k0 = 0; k0 < K; k0 += BK) {
        {
            const float* fx = (const float*)af;
            __nv_bfloat16 hbuf[16], lbuf[16];
#pragma unroll
            for (int i = 0; i < 16; i++) split_bf16(fx[i], hbuf[i], lbuf[i]);
            *(uint4*)&AsH[arow * LDS_ + aseg]     = *(const uint4*)&hbuf[0];
            *(uint4*)&AsH[arow * LDS_ + aseg + 8] = *(const uint4*)&hbuf[8];
            *(uint4*)&AsL[arow * LDS_ + aseg]     = *(const uint4*)&lbuf[0];
            *(uint4*)&AsL[arow * LDS_ + aseg + 8] = *(const uint4*)&lbuf[8];
#pragma unroll
            for (int c = 0; c < NCH; c++) {
                int ch = t + c * 256;
                if (ch < BCH) {
                    int brow = ch >> 2, bseg = (ch & 3) * 8;
                    *(uint4*)&BsH[brow * LDS_ + bseg] = bhv[c];
                    *(uint4*)&BsL[brow * LDS_ + bseg] = blv[c];
                }
            }
        }
        __syncthreads();

        if (k0 + BK < K) {
            const float* src = A + (size_t)(blockRow + arow) * K + k0 + BK + aseg;
#pragma unroll
            for (int i = 0; i < 4; i++) af[i] = *(const float4*)(src + i * 4);
#pragma unroll
            for (int c = 0; c < NCH; c++) {
                int ch = t + c * 256;
                if (ch < BCH) {
                    int brow = ch >> 2, bseg = (ch & 3) * 8;
                    bhv[c] = *(const uint4*)(BtHi + (size_t)(blockCol + brow) * K + k0 + BK + bseg);
                    blv[c] = *(const uint4*)(BtLo + (size_t)(blockCol + brow) * K + k0 + BK + bseg);
                }
            }
        }

#pragma unroll
        for (int ks = 0; ks < 2; ks++) {
            const int kb = ks * 16;
            uint32_t aH[2][4], aL[2][4];
#pragma unroll
            for (int mt = 0; mt < 2; mt++) {
                int m0 = wm * 32 + mt * 16;
                aH[mt][0] = *(const uint32_t*)&AsH[(m0 + g) * LDS_ + kb + 2 * q];
                aH[mt][1] = *(const uint32_t*)&AsH[(m0 + g + 8) * LDS_ + kb + 2 * q];
                aH[mt][2] = *(const uint32_t*)&AsH[(m0 + g) * LDS_ + kb + 2 * q + 8];
                aH[mt][3] = *(const uint32_t*)&AsH[(m0 + g + 8) * LDS_ + kb + 2 * q + 8];
                aL[mt][0] = *(const uint32_t*)&AsL[(m0 + g) * LDS_ + kb + 2 * q];
                aL[mt][1] = *(const uint32_t*)&AsL[(m0 + g + 8) * LDS_ + kb + 2 * q];
                aL[mt][2] = *(const uint32_t*)&AsL[(m0 + g) * LDS_ + kb + 2 * q + 8];
                aL[mt][3] = *(const uint32_t*)&AsL[(m0 + g + 8) * LDS_ + kb + 2 * q + 8];
            }
            uint32_t bH[NT][2], bL[NT][2];
#pragma unroll
            for (int nt = 0; nt < NT; nt++) {
                int n0 = wn * WN + nt * 8 + g;
                bH[nt][0] = *(const uint32_t*)&BsH[n0 * LDS_ + kb + 2 * q];
                bH[nt][1] = *(const uint32_t*)&BsH[n0 * LDS_ + kb + 2 * q + 8];
                bL[nt][0] = *(const uint32_t*)&BsL[n0 * LDS_ + kb + 2 * q];
                bL[nt][1] = *(const uint32_t*)&BsL[n0 * LDS_ + kb + 2 * q + 8];
            }
#pragma unroll
            for (int mt = 0; mt < 2; mt++)
#pragma unroll
                for (int nt = 0; nt < NT; nt++) {
                    mma_bf16(acc[mt][nt], aH[mt], bH[nt]);
                    mma_bf16(acc[mt][nt], aH[mt], bL[nt]);
                    mma_bf16(acc[mt][nt], aL[mt], bH[nt]);
                }
        }
        __syncthreads();
    }

    // epilogue
#pragma unroll
    for (int mt = 0; mt < 2; mt++) {
        int row = blockRow + wm * 32 + mt * 16 + g;
#pragma unroll
        for (int nt = 0; nt < NT; nt++) {
            int col = blockCol + wn * WN + nt * 8 + 2 * q;
            float2 bb = make_float2(0.f, 0.f);
            if (bias) bb = *(const float2*)&bias[col];
            float v00 = acc[mt][nt][0] + bb.x, v01 = acc[mt][nt][1] + bb.y;
            float v10 = acc[mt][nt][2] + bb.x, v11 = acc[mt][nt][3] + bb.y;
            if (HALF_OUT) {
                __half2* Ch = (__half2*)Cout;
                Ch[((size_t)row * N + col) >> 1]       = __floats2half2_rn(v00, v01);
                Ch[((size_t)(row + 8) * N + col) >> 1] = __floats2half2_rn(v10, v11);
            } else {
                float* Cf = (float*)Cout;
                *(float2*)&Cf[(size_t)row * N + col]       = make_float2(v00, v01);
                *(float2*)&Cf[(size_t)(row + 8) * N + col] = make_float2(v10, v11);
            }
        }
    }
}

// -------------------- prep: vmean + Wv/Wo transpose-split + bias fold ------
__global__ void prep_kernel(const float* __restrict__ v,
                            const float* __restrict__ Wv,
                            const float* __restrict__ Wo,
                            const float* __restrict__ bq,
                            const float* __restrict__ Woff,
                            const float* __restrict__ boff,
                            const float* __restrict__ Wattn,
                            const float* __restrict__ battn) {
    const int VT = Nn * Cc / 4;            // 262144 float4 lanes
    const int WT = Cc * Cc;                // 65536
    int idx = blockIdx.x * blockDim.x + threadIdx.x;
    if (idx < VT) {
        const float4* v4 = reinterpret_cast<const float4*>(v);
        float4 a = v4[idx], b = v4[idx + VT], c = v4[idx + 2 * VT], d = v4[idx + 3 * VT];
        float4 r;
        r.x = 0.25f * (a.x + b.x + c.x + d.x);
        r.y = 0.25f * (a.y + b.y + c.y + d.y);
        r.z = 0.25f * (a.z + b.z + c.z + d.z);
        r.w = 0.25f * (a.w + b.w + c.w + d.w);
        reinterpret_cast<float4*>(g_vmean)[idx] = r;
    } else if (idx < VT + WT) {
        int li = idx - VT;
        int n = li / Cc, k = li % Cc;
        split_bf16(Wv[k * Cc + n], g_WvT_hi[li], g_WvT_lo[li]);
    } else if (idx < VT + 2 * WT) {
        int li = idx - VT - WT;
        int n = li / Cc, k = li % Cc;
        split_bf16(Wo[k * Cc + n], g_WoT_hi[li], g_WoT_lo[li]);
    } else if (idx < VT + 2 * WT + 96) {
        int j = idx - VT - 2 * WT;
        if (j < 64) {
            float s = boff[j];
            for (int k = 0; k < Cc; k++) s += bq[k] * Woff[k * 64 + j];
            g_bfold[j] = s;
        } else {
            int jj = j - 64;
            float s = battn[jj];
            for (int k = 0; k < Cc; k++) s += bq[k] * Wattn[k * 32 + jj];
            g_bfold[j] = s;
        }
    }
}

// -------------------- fold: WfT[c][k] = split(sum_j Wq[k][j]*Wcat[j][c]) ---
__global__ void fold_kernel(const float* __restrict__ Wq,
                            const float* __restrict__ Woff,
                            const float* __restrict__ Wattn) {
    int idx = blockIdx.x * blockDim.x + threadIdx.x;   // 256*96
    if (idx >= Cc * 96) return;
    int k = idx / 96, c = idx % 96;
    const float* wq = Wq + k * Cc;
    float s = 0.f;
    if (c < 64) {
#pragma unroll 8
        for (int j = 0; j < Cc; j++) s = fmaf(wq[j], Woff[j * 64 + c], s);
    } else {
        int cc2 = c - 64;
#pragma unroll 8
        for (int j = 0; j < Cc; j++) s = fmaf(wq[j], Wattn[j * 32 + cc2], s);
    }
    split_bf16(s, g_WfT_hi[c * Cc + k], g_WfT_lo[c * Cc + k]);
}

// -------------------- sampling (fp16 feature map) --------------------------
__global__ void __launch_bounds__(256) sample_kernel() {
    __shared__ float s_off[8][64];
    __shared__ float s_attn[8][32];
    const int w    = threadIdx.x >> 5;
    const int lane = threadIdx.x & 31;
    const int row  = blockIdx.x * 8 + w;

    const float* oarow = g_offattn + (size_t)row * 96;
    s_off[w][lane]      = oarow[lane];
    s_off[w][lane + 32] = oarow[lane + 32];
    s_attn[w][lane]     = oarow[64 + lane];
    __syncwarp();

    const int n = row & (Nn - 1);
    const float refx = (float)(n & (GW - 1)) * (1.0f / 63.0f);
    const float refy = (float)(n >> 6) * (1.0f / 63.0f);
    float* outrow = g_pre + (size_t)row * Cc;

#pragma unroll
    for (int h = 0; h < NHh; h++) {
        float l0 = s_attn[w][h * 4 + 0];
        float l1 = s_attn[w][h * 4 + 1];
        float l2 = s_attn[w][h * 4 + 2];
        float l3 = s_attn[w][h * 4 + 3];
        float m  = fmaxf(fmaxf(l0, l1), fmaxf(l2, l3));
        float e0 = __expf(l0 - m), e1 = __expf(l1 - m);
        float e2 = __expf(l2 - m), e3 = __expf(l3 - m);
        float inv = 1.0f / (e0 + e1 + e2 + e3);
        float wp[4] = {e0 * inv, e1 * inv, e2 * inv, e3 * inv};

        const __half* fmap = g_vpm_h + h * HDd + lane;
        float acc = 0.f;
#pragma unroll
        for (int p = 0; p < NPp; p++) {
            float ox = s_off[w][h * 8 + p * 2 + 0];
            float oy = s_off[w][h * 8 + p * 2 + 1];
            float lx = fminf(fmaxf(refx + ox, 0.f), 1.f);
            float ly = fminf(fmaxf(refy + oy, 0.f), 1.f);
            float x = lx * (float)GW - 0.5f;
            float y = ly * (float)GW - 0.5f;
            float xf = floorf(x), yf = floorf(y);
            float tx = x - xf, ty = y - yf;
            int x0 = (int)xf, y0 = (int)yf;
            int x1 = x0 + 1, y1 = y0 + 1;
            bool vx0 = (x0 >= 0), vx1 = (x1 < GW);
            bool vy0 = (y0 >= 0), vy1 = (y1 < GW);
            float w00 = (1.f - tx) * (1.f - ty);
            float w01 = tx * (1.f - ty);
            float w10 = (1.f - tx) * ty;
            float w11 = tx * ty;
            float a = 0.f;
            if (vx0 && vy0) a = fmaf(w00, __half2float(fmap[(size_t)(y0 * GW + x0) * Cc]), a);
            if (vx1 && vy0) a = fmaf(w01, __half2float(fmap[(size_t)(y0 * GW + x1) * Cc]), a);
            if (vx0 && vy1) a = fmaf(w10, __half2float(fmap[(size_t)(y1 * GW + x0) * Cc]), a);
            if (vx1 && vy1) a = fmaf(w11, __half2float(fmap[(size_t)(y1 * GW + x1) * Cc]), a);
            acc = fmaf(wp[p], a, acc);
        }
        outrow[h * HDd + lane] = acc;
    }
}

// ---------------------------------------------------------------------------
extern "C" void kernel_launch(void* const* d_in, const int* in_sizes, int n_in,
                              void* d_out, int out_size) {
    (void)in_sizes; (void)n_in; (void)out_size;
    const float* q     = (const float*)d_in[0];
    const float* v     = (const float*)d_in[2];
    const float* Wq    = (const float*)d_in[3];
    const float* bq    = (const float*)d_in[4];
    const float* Wv    = (const float*)d_in[7];
    const float* bv    = (const float*)d_in[8];
    const float* Wo    = (const float*)d_in[9];
    const float* bo    = (const float*)d_in[10];
    const float* Woff  = (const float*)d_in[11];
    const float* boff  = (const float*)d_in[12];
    const float* Wattn = (const float*)d_in[13];
    const float* battn = (const float*)d_in[14];
    float* out = (float*)d_out;

    float *p_vmean, *p_bfold, *p_offattn, *p_pre;
    __half* p_vpmh;
    __nv_bfloat16 *p_WvH, *p_WvL, *p_WoH, *p_WoL, *p_WfH, *p_WfL;
    cudaGetSymbolAddress((void**)&p_vmean,   g_vmean);
    cudaGetSymbolAddress((void**)&p_vpmh,    g_vpm_h);
    cudaGetSymbolAddress((void**)&p_bfold,   g_bfold);
    cudaGetSymbolAddress((void**)&p_offattn, g_offattn);
    cudaGetSymbolAddress((void**)&p_pre,     g_pre);
    cudaGetSymbolAddress((void**)&p_WvH,     g_WvT_hi);
    cudaGetSymbolAddress((void**)&p_WvL,     g_WvT_lo);
    cudaGetSymbolAddress((void**)&p_WoH,     g_WoT_hi);
    cudaGetSymbolAddress((void**)&p_WoL,     g_WoT_lo);
    cudaGetSymbolAddress((void**)&p_WfH,     g_WfT_hi);
    cudaGetSymbolAddress((void**)&p_WfL,     g_WfT_lo);

    // 1. fused prep (vmean, Wv/Wo transpose-split, bias fold)
    {
        int tot = Nn * Cc / 4 + 2 * Cc * Cc + 96;
        prep_kernel<<<(tot + 255) / 256, 256>>>(v, Wv, Wo, bq, Woff, boff,
                                                Wattn, battn);
    }

    // 2. weight fold (writes split-transposed bf16 directly)
    fold_kernel<<<(Cc * 96 + 255) / 256, 256>>>(Wq, Woff, Wattn);

    // 3. offattn = q @ Wfold + bfold
    gemm_bf16x3<96, false><<<dim3(1, ROWS / 128), 256>>>(
        q, p_WfH, p_WfL, p_bfold, p_offattn, ROWS, 96);

    // 4. vpm (fp16) = vmean @ Wv + bv   [ncu capture slot]
    gemm_bf16x3<64, true><<<dim3(Cc / 64, Nn / 128), 256>>>(
        p_vmean, p_WvH, p_WvL, bv, p_vpmh, Nn, Cc);

    // 5. sampling
    sample_kernel<<<ROWS / 8, 256>>>();

    // 6. out = pre @ Wo + bo
    gemm_bf16x3<64, false><<<dim3(Cc / 64, ROWS / 128), 256>>>(
        p_pre, p_WoH, p_WoL, bo, out, ROWS, Cc);
}

// round 4
// speedup vs baseline: 1.1360x; 1.1360x over previous
#include <cuda_runtime.h>
#include <cuda_bf16.h>
#include <cuda_fp16.h>
#include <cstdint>

// ---------------------------------------------------------------------------
// DeformableAttention (B=8, N=4096, C=256, S=4, NH=8, NL=1, NP=4, HD=32)
//
// bf16x3 split tensor-core pipeline v2: pre-split A operands, cp.async
// double-buffered GEMM with ldmatrix + XOR swizzle.
//   1. prep: split q -> qh/ql; vmean=mean_s v -> vmh/vml;
//            transpose+split Wv,Wo; bias fold (padded to 128)
//   2. fold: WfT = (Wq @ [Woff|Wattn])^T split, padded N=128
//   3. offattn = q @ Wfold + bfold           (32768 x 128, fp32)
//   4. vpm     = vmean @ Wv + bv             (4096 x 256, fp16)   [ncu slot]
//   5. sampling -> pre split bf16 hi/lo      (32768 x 256)
//   6. out     = pre @ Wo + bo               (32768 x 256, fp32)
// ---------------------------------------------------------------------------

namespace {
constexpr int Bn   = 8;
constexpr int Nn   = 4096;
constexpr int Cc   = 256;   // K for all GEMMs
constexpr int NHh  = 8;
constexpr int NPp  = 4;
constexpr int HDd  = 32;
constexpr int ROWS = Bn * Nn;    // 32768
constexpr int GW   = 64;
constexpr int NF   = 128;        // padded offattn width
}

// -------------------- scratch (static device globals) ----------------------
__device__ __align__(16) __nv_bfloat16 g_qh[(size_t)ROWS * Cc];
__device__ __align__(16) __nv_bfloat16 g_ql[(size_t)ROWS * Cc];
__device__ __align__(16) __nv_bfloat16 g_vmh[Nn * Cc];
__device__ __align__(16) __nv_bfloat16 g_vml[Nn * Cc];
__device__ __align__(16) __half g_vpm_h[Nn * Cc];
__device__ __align__(16) float g_bfold[NF];
__device__ __align__(16) __nv_bfloat16 g_WvT_hi[Cc * Cc];
__device__ __align__(16) __nv_bfloat16 g_WvT_lo[Cc * Cc];
__device__ __align__(16) __nv_bfloat16 g_WoT_hi[Cc * Cc];
__device__ __align__(16) __nv_bfloat16 g_WoT_lo[Cc * Cc];
__device__ __align__(16) __nv_bfloat16 g_WfT_hi[NF * Cc];
__device__ __align__(16) __nv_bfloat16 g_WfT_lo[NF * Cc];
__device__ __align__(16) float g_offattn[(size_t)ROWS * NF];
__device__ __align__(16) __nv_bfloat16 g_preh[(size_t)ROWS * Cc];
__device__ __align__(16) __nv_bfloat16 g_prel[(size_t)ROWS * Cc];

// -------------------- helpers ----------------------------------------------
__device__ __forceinline__ void mma_bf16(float c[4], const uint32_t a[4],
                                         const uint32_t b[2]) {
    asm volatile(
        "mma.sync.aligned.m16n8k16.row.col.f32.bf16.bf16.f32 "
        "{%0,%1,%2,%3}, {%4,%5,%6,%7}, {%8,%9}, {%0,%1,%2,%3};\n"
        : "+f"(c[0]), "+f"(c[1]), "+f"(c[2]), "+f"(c[3])
        : "r"(a[0]), "r"(a[1]), "r"(a[2]), "r"(a[3]), "r"(b[0]), "r"(b[1]));
}

__device__ __forceinline__ void ldmx4(uint32_t r[4], uint32_t addr) {
    asm volatile(
        "ldmatrix.sync.aligned.m8n8.x4.shared.b16 {%0,%1,%2,%3}, [%4];\n"
        : "=r"(r[0]), "=r"(r[1]), "=r"(r[2]), "=r"(r[3]) : "r"(addr));
}

__device__ __forceinline__ void cp_async16(uint32_t dst, const void* src) {
    asm volatile("cp.async.cg.shared.global [%0], [%1], 16;\n"
                 :: "r"(dst), "l"(src));
}
__device__ __forceinline__ void cp_commit() {
    asm volatile("cp.async.commit_group;\n");
}
template <int NN>
__device__ __forceinline__ void cp_wait() {
    asm volatile("cp.async.wait_group %0;\n" :: "n"(NN));
}

__device__ __forceinline__ void split_bf16(float x, __nv_bfloat16& h,
                                           __nv_bfloat16& l) {
    h = __float2bfloat16(x);
    l = __float2bfloat16(x - __bfloat162float(h));
}

// -------------------- GEMM: C = (Ah+Al) @ (Bh+Bl)^T + bias ----------------
// All operands bf16 [rows][K=256] K-major. 3-term split accumulation.
// BM=128, BN=64, BK=32, double-buffered cp.async, ldmatrix, XOR swizzle.
// smem layout (bytes): AH[buf]=buf*8192, AL=16384+buf*8192,
//                      BH=32768+buf*4096, BL=40960+buf*4096. Total 48KB.
template <bool HALF_OUT>
__global__ void __launch_bounds__(256, 2)
gemm_splitmma(const __nv_bfloat16* __restrict__ Agh,
              const __nv_bfloat16* __restrict__ Agl,
              const __nv_bfloat16* __restrict__ Bgh,
              const __nv_bfloat16* __restrict__ Bgl,
              const float* __restrict__ bias, void* __restrict__ Cout,
              int M, int N) {
    constexpr int K = Cc, BM = 128, BN = 64, BK = 32;
    constexpr int NK = K / BK;     // 8
    __shared__ __align__(128) uint8_t smem[49152];
    const uint32_t sb = (uint32_t)__cvta_generic_to_shared(smem);

    const int t = threadIdx.x, w = t >> 5, l = t & 31;
    const int wm = w & 3, wn = w >> 2;
    const int g = l >> 2, qq = l & 3;
    const int blockRow = blockIdx.y * BM;
    const int blockCol = blockIdx.x * BN;

    const int lr = t >> 2, lc = t & 3;   // staging row/chunk

    float acc[2][4][4];
#pragma unroll
    for (int i = 0; i < 2; i++)
#pragma unroll
        for (int j = 0; j < 4; j++)
#pragma unroll
            for (int x = 0; x < 4; x++) acc[i][j][x] = 0.f;

    auto stage = [&](int buf, int k0) {
        const uint32_t ah = sb + buf * 8192;
        const uint32_t al = sb + 16384 + buf * 8192;
        const uint32_t bh = sb + 32768 + buf * 4096;
        const uint32_t bl = sb + 40960 + buf * 4096;
#pragma unroll
        for (int j = 0; j < 2; j++) {
            int row = lr + j * 64;
            uint32_t sw = (uint32_t)row * 64 + (uint32_t)((lc ^ ((row >> 1) & 3)) * 16);
            size_t goff = (size_t)(blockRow + row) * K + k0 + lc * 8;
            cp_async16(ah + sw, Agh + goff);
            cp_async16(al + sw, Agl + goff);
        }
        {
            uint32_t sw = (uint32_t)lr * 64 + (uint32_t)((lc ^ ((lr >> 1) & 3)) * 16);
            size_t goff = (size_t)(blockCol + lr) * K + k0 + lc * 8;
            cp_async16(bh + sw, Bgh + goff);
            cp_async16(bl + sw, Bgl + goff);
        }
        cp_commit();
    };

    auto compute = [&](int buf) {
        const uint32_t ahb = sb + buf * 8192;
        const uint32_t alb = sb + 16384 + buf * 8192;
        const uint32_t bhb = sb + 32768 + buf * 4096;
        const uint32_t blb = sb + 40960 + buf * 4096;
        const int seg = l >> 3, sl = l & 7;
#pragma unroll
        for (int ks = 0; ks < 2; ks++) {
            uint32_t aH[2][4], aL[2][4];
#pragma unroll
            for (int mt = 0; mt < 2; mt++) {
                int r = wm * 32 + mt * 16 + (seg & 1) * 8 + sl;
                int c = ks * 2 + (seg >> 1);
                uint32_t addr = (uint32_t)r * 64 + (uint32_t)((c ^ ((r >> 1) & 3)) * 16);
                ldmx4(aH[mt], ahb + addr);
                ldmx4(aL[mt], alb + addr);
            }
            uint32_t bH[4][2], bL[4][2];
#pragma unroll
            for (int nt = 0; nt < 2; nt++) {
                int r = wn * 32 + nt * 16 + (seg >> 1) * 8 + sl;
                int c = ks * 2 + (seg & 1);
                uint32_t addr = (uint32_t)r * 64 + (uint32_t)((c ^ ((r >> 1) & 3)) * 16);
                uint32_t tmp[4];
                ldmx4(tmp, bhb + addr);
                bH[nt * 2][0] = tmp[0]; bH[nt * 2][1] = tmp[1];
                bH[nt * 2 + 1][0] = tmp[2]; bH[nt * 2 + 1][1] = tmp[3];
                ldmx4(tmp, blb + addr);
                bL[nt * 2][0] = tmp[0]; bL[nt * 2][1] = tmp[1];
                bL[nt * 2 + 1][0] = tmp[2]; bL[nt * 2 + 1][1] = tmp[3];
            }
#pragma unroll
            for (int mt = 0; mt < 2; mt++)
#pragma unroll
                for (int nf = 0; nf < 4; nf++) {
                    mma_bf16(acc[mt][nf], aH[mt], bH[nf]);
                    mma_bf16(acc[mt][nf], aH[mt], bL[nf]);
                    mma_bf16(acc[mt][nf], aL[mt], bH[nf]);
                }
        }
    };

    stage(0, 0);
    for (int kt = 0; kt < NK; kt++) {
        if (kt + 1 < NK) {
            stage((kt + 1) & 1, (kt + 1) * BK);
            cp_wait<1>();
        } else {
            cp_wait<0>();
        }
        __syncthreads();
        compute(kt & 1);
        __syncthreads();
    }

    // epilogue
#pragma unroll
    for (int mt = 0; mt < 2; mt++) {
        int row = blockRow + wm * 32 + mt * 16 + g;
#pragma unroll
        for (int nf = 0; nf < 4; nf++) {
            int col = blockCol + wn * 32 + nf * 8 + 2 * qq;
            float2 bb = *(const float2*)&bias[col];
            float v00 = acc[mt][nf][0] + bb.x, v01 = acc[mt][nf][1] + bb.y;
            float v10 = acc[mt][nf][2] + bb.x, v11 = acc[mt][nf][3] + bb.y;
            if (HALF_OUT) {
                __half2* Ch = (__half2*)Cout;
                Ch[((size_t)row * N + col) >> 1]       = __floats2half2_rn(v00, v01);
                Ch[((size_t)(row + 8) * N + col) >> 1] = __floats2half2_rn(v10, v11);
            } else {
                float* Cf = (float*)Cout;
                *(float2*)&Cf[(size_t)row * N + col]       = make_float2(v00, v01);
                *(float2*)&Cf[(size_t)(row + 8) * N + col] = make_float2(v10, v11);
            }
        }
    }
}

// -------------------- prep: q split + vmean split + W transposes + bias ----
__global__ void prep_kernel(const float* __restrict__ q,
                            const float* __restrict__ v,
                            const float* __restrict__ Wv,
                            const float* __restrict__ Wo,
                            const float* __restrict__ bq,
                            const float* __restrict__ Woff,
                            const float* __restrict__ boff,
                            const float* __restrict__ Wattn,
                            const float* __restrict__ battn) {
    const int QT = ROWS * Cc / 4;          // 2097152
    const int VT = Nn * Cc / 4;            // 262144
    const int WT = Cc * Cc;                // 65536
    int idx = blockIdx.x * blockDim.x + threadIdx.x;
    if (idx < QT) {
        float4 a = reinterpret_cast<const float4*>(q)[idx];
        __nv_bfloat16 h[4], lo[4];
        split_bf16(a.x, h[0], lo[0]);
        split_bf16(a.y, h[1], lo[1]);
        split_bf16(a.z, h[2], lo[2]);
        split_bf16(a.w, h[3], lo[3]);
        *(uint2*)&g_qh[(size_t)idx * 4] = *(const uint2*)h;
        *(uint2*)&g_ql[(size_t)idx * 4] = *(const uint2*)lo;
    } else if (idx < QT + VT) {
        int li = idx - QT;
        const float4* v4 = reinterpret_cast<const float4*>(v);
        float4 a = v4[li], b = v4[li + VT], c = v4[li + 2 * VT], d = v4[li + 3 * VT];
        float4 r;
        r.x = 0.25f * (a.x + b.x + c.x + d.x);
        r.y = 0.25f * (a.y + b.y + c.y + d.y);
        r.z = 0.25f * (a.z + b.z + c.z + d.z);
        r.w = 0.25f * (a.w + b.w + c.w + d.w);
        __nv_bfloat16 h[4], lo[4];
        split_bf16(r.x, h[0], lo[0]);
        split_bf16(r.y, h[1], lo[1]);
        split_bf16(r.z, h[2], lo[2]);
        split_bf16(r.w, h[3], lo[3]);
        *(uint2*)&g_vmh[li * 4] = *(const uint2*)h;
        *(uint2*)&g_vml[li * 4] = *(const uint2*)lo;
    } else if (idx < QT + VT + WT) {
        int li = idx - QT - VT;
        int n = li / Cc, k = li % Cc;
        split_bf16(Wv[k * Cc + n], g_WvT_hi[li], g_WvT_lo[li]);
    } else if (idx < QT + VT + 2 * WT) {
        int li = idx - QT - VT - WT;
        int n = li / Cc, k = li % Cc;
        split_bf16(Wo[k * Cc + n], g_WoT_hi[li], g_WoT_lo[li]);
    } else if (idx < QT + VT + 2 * WT + NF) {
        int j = idx - QT - VT - 2 * WT;
        if (j < 64) {
            float s = boff[j];
            for (int k = 0; k < Cc; k++) s += bq[k] * Woff[k * 64 + j];
            g_bfold[j] = s;
        } else if (j < 96) {
            int jj = j - 64;
            float s = battn[jj];
            for (int k = 0; k < Cc; k++) s += bq[k] * Wattn[k * 32 + jj];
            g_bfold[j] = s;
        } else {
            g_bfold[j] = 0.f;
        }
    }
}

// -------------------- fold: WfT[c][k] (padded to NF rows) ------------------
__global__ void fold_kernel(const float* __restrict__ Wq,
                            const float* __restrict__ Woff,
                            const float* __restrict__ Wattn) {
    int idx = blockIdx.x * blockDim.x + threadIdx.x;   // NF*256
    if (idx >= NF * Cc) return;
    int k = idx / NF, c = idx % NF;
    float s = 0.f;
    if (c < 96) {
        const float* wq = Wq + k * Cc;
        if (c < 64) {
#pragma unroll 8
            for (int j = 0; j < Cc; j++) s = fmaf(wq[j], Woff[j * 64 + c], s);
        } else {
            int cc2 = c - 64;
#pragma unroll 8
            for (int j = 0; j < Cc; j++) s = fmaf(wq[j], Wattn[j * 32 + cc2], s);
        }
    }
    split_bf16(s, g_WfT_hi[c * Cc + k], g_WfT_lo[c * Cc + k]);
}

// -------------------- sampling (fp16 map, bf16 hi/lo output) ---------------
__global__ void __launch_bounds__(256) sample_kernel() {
    __shared__ float s_off[8][64];
    __shared__ float s_attn[8][32];
    const int w    = threadIdx.x >> 5;
    const int lane = threadIdx.x & 31;
    const int row  = blockIdx.x * 8 + w;

    const float* oarow = g_offattn + (size_t)row * NF;
    s_off[w][lane]      = oarow[lane];
    s_off[w][lane + 32] = oarow[lane + 32];
    s_attn[w][lane]     = oarow[64 + lane];
    __syncwarp();

    const int n = row & (Nn - 1);
    const float refx = (float)(n & (GW - 1)) * (1.0f / 63.0f);
    const float refy = (float)(n >> 6) * (1.0f / 63.0f);

#pragma unroll
    for (int h = 0; h < NHh; h++) {
        float l0 = s_attn[w][h * 4 + 0];
        float l1 = s_attn[w][h * 4 + 1];
        float l2 = s_attn[w][h * 4 + 2];
        float l3 = s_attn[w][h * 4 + 3];
        float m  = fmaxf(fmaxf(l0, l1), fmaxf(l2, l3));
        float e0 = __expf(l0 - m), e1 = __expf(l1 - m);
        float e2 = __expf(l2 - m), e3 = __expf(l3 - m);
        float inv = 1.0f / (e0 + e1 + e2 + e3);
        float wp[4] = {e0 * inv, e1 * inv, e2 * inv, e3 * inv};

        const __half* fmap = g_vpm_h + h * HDd + lane;
        float acc = 0.f;
#pragma unroll
        for (int p = 0; p < NPp; p++) {
            float ox = s_off[w][h * 8 + p * 2 + 0];
            float oy = s_off[w][h * 8 + p * 2 + 1];
            float lx = fminf(fmaxf(refx + ox, 0.f), 1.f);
            float ly = fminf(fmaxf(refy + oy, 0.f), 1.f);
            float x = lx * (float)GW - 0.5f;
            float y = ly * (float)GW - 0.5f;
            float xf = floorf(x), yf = floorf(y);
            float tx = x - xf, ty = y - yf;
            int x0 = (int)xf, y0 = (int)yf;
            int x1 = x0 + 1, y1 = y0 + 1;
            bool vx0 = (x0 >= 0), vx1 = (x1 < GW);
            bool vy0 = (y0 >= 0), vy1 = (y1 < GW);
            float w00 = (1.f - tx) * (1.f - ty);
            float w01 = tx * (1.f - ty);
            float w10 = (1.f - tx) * ty;
            float w11 = tx * ty;
            float a = 0.f;
            if (vx0 && vy0) a = fmaf(w00, __half2float(fmap[(size_t)(y0 * GW + x0) * Cc]), a);
            if (vx1 && vy0) a = fmaf(w01, __half2float(fmap[(size_t)(y0 * GW + x1) * Cc]), a);
            if (vx0 && vy1) a = fmaf(w10, __half2float(fmap[(size_t)(y1 * GW + x0) * Cc]), a);
            if (vx1 && vy1) a = fmaf(w11, __half2float(fmap[(size_t)(y1 * GW + x1) * Cc]), a);
            acc = fmaf(wp[p], a, acc);
        }
        __nv_bfloat16 hh, ll;
        split_bf16(acc, hh, ll);
        g_preh[(size_t)row * Cc + h * HDd + lane] = hh;
        g_prel[(size_t)row * Cc + h * HDd + lane] = ll;
    }
}

// ---------------------------------------------------------------------------
extern "C" void kernel_launch(void* const* d_in, const int* in_sizes, int n_in,
                              void* d_out, int out_size) {
    (void)in_sizes; (void)n_in; (void)out_size;
    const float* q     = (const float*)d_in[0];
    const float* v     = (const float*)d_in[2];
    const float* Wq    = (const float*)d_in[3];
    const float* bq    = (const float*)d_in[4];
    const float* Wv    = (const float*)d_in[7];
    const float* bv    = (const float*)d_in[8];
    const float* Wo    = (const float*)d_in[9];
    const float* bo    = (const float*)d_in[10];
    const float* Woff  = (const float*)d_in[11];
    const float* boff  = (const float*)d_in[12];
    const float* Wattn = (const float*)d_in[13];
    const float* battn = (const float*)d_in[14];
    float* out = (float*)d_out;

    float *p_bfold, *p_offattn;
    __half* p_vpmh;
    __nv_bfloat16 *p_qh, *p_ql, *p_vmh, *p_vml, *p_preh, *p_prel;
    __nv_bfloat16 *p_WvH, *p_WvL, *p_WoH, *p_WoL, *p_WfH, *p_WfL;
    cudaGetSymbolAddress((void**)&p_qh,      g_qh);
    cudaGetSymbolAddress((void**)&p_ql,      g_ql);
    cudaGetSymbolAddress((void**)&p_vmh,     g_vmh);
    cudaGetSymbolAddress((void**)&p_vml,     g_vml);
    cudaGetSymbolAddress((void**)&p_vpmh,    g_vpm_h);
    cudaGetSymbolAddress((void**)&p_bfold,   g_bfold);
    cudaGetSymbolAddress((void**)&p_offattn, g_offattn);
    cudaGetSymbolAddress((void**)&p_preh,    g_preh);
    cudaGetSymbolAddress((void**)&p_prel,    g_prel);
    cudaGetSymbolAddress((void**)&p_WvH,     g_WvT_hi);
    cudaGetSymbolAddress((void**)&p_WvL,     g_WvT_lo);
    cudaGetSymbolAddress((void**)&p_WoH,     g_WoT_hi);
    cudaGetSymbolAddress((void**)&p_WoL,     g_WoT_lo);
    cudaGetSymbolAddress((void**)&p_WfH,     g_WfT_hi);
    cudaGetSymbolAddress((void**)&p_WfL,     g_WfT_lo);

    // 1. fused prep
    {
        int tot = ROWS * Cc / 4 + Nn * Cc / 4 + 2 * Cc * Cc + NF;
        prep_kernel<<<(tot + 255) / 256, 256>>>(q, v, Wv, Wo, bq, Woff, boff,
                                                Wattn, battn);
    }

    // 2. weight fold
    fold_kernel<<<(NF * Cc + 255) / 256, 256>>>(Wq, Woff, Wattn);

    // 3. offattn = q @ Wfold + bfold  (N padded to 128)
    gemm_splitmma<false><<<dim3(NF / 64, ROWS / 128), 256>>>(
        p_qh, p_ql, p_WfH, p_WfL, p_bfold, p_offattn, ROWS, NF);

    // 4. vpm (fp16) = vmean @ Wv + bv   [ncu capture slot]
    gemm_splitmma<true><<<dim3(Cc / 64, Nn / 128), 256>>>(
        p_vmh, p_vml, p_WvH, p_WvL, bv, p_vpmh, Nn, Cc);

    // 5. sampling
    sample_kernel<<<ROWS / 8, 256>>>();

    // 6. out = pre @ Wo + bo
    gemm_splitmma<false><<<dim3(Cc / 64, ROWS / 128), 256>>>(
        p_preh, p_prel, p_WoH, p_WoL, bo, out, ROWS, Cc);
}